// round 2
// baseline (speedup 1.0000x reference)
#include <cuda_runtime.h>

// out[r] = dot(W1[i1[r]], W2[i2[r]]) + b1[i1[r]] + b2[i2[r]]
// 8 lanes per row: lane loads 4 float4 from each table row (MLP=8 LDG.128),
// 3-level shuffle reduction, bias loads overlapped with row loads.

#define BATCH 16384
#define EMBED 128  // 32 float4 per row

__global__ __launch_bounds__(256)
void fused_embed_dot_kernel(const int* __restrict__ i1,
                            const int* __restrict__ i2,
                            const float* __restrict__ W1,
                            const float* __restrict__ W2,
                            const float* __restrict__ b1,
                            const float* __restrict__ b2,
                            float* __restrict__ out) {
    int t   = blockIdx.x * blockDim.x + threadIdx.x;
    int row = t >> 3;        // 8 threads per row
    int sub = t & 7;         // 0..7

    int idx1 = __ldg(&i1[row]);
    int idx2 = __ldg(&i2[row]);

    // Issue bias loads early — broadcast 4B loads, overlap with row gathers.
    float bv1 = __ldg(&b1[idx1]);
    float bv2 = __ldg(&b2[idx2]);

    const float4* r1 = reinterpret_cast<const float4*>(W1 + idx1 * EMBED);
    const float4* r2 = reinterpret_cast<const float4*>(W2 + idx2 * EMBED);

    // 8 independent LDG.128 per lane, front-batched by ptxas.
    float4 a0 = __ldg(&r1[sub +  0]);
    float4 a1 = __ldg(&r1[sub +  8]);
    float4 a2 = __ldg(&r1[sub + 16]);
    float4 a3 = __ldg(&r1[sub + 24]);
    float4 c0 = __ldg(&r2[sub +  0]);
    float4 c1 = __ldg(&r2[sub +  8]);
    float4 c2 = __ldg(&r2[sub + 16]);
    float4 c3 = __ldg(&r2[sub + 24]);

    // Two accumulator chains for FMA ILP.
    float acc0 = a0.x * c0.x;
    float acc1 = a1.x * c1.x;
    acc0 = fmaf(a0.y, c0.y, acc0);  acc1 = fmaf(a1.y, c1.y, acc1);
    acc0 = fmaf(a0.z, c0.z, acc0);  acc1 = fmaf(a1.z, c1.z, acc1);
    acc0 = fmaf(a0.w, c0.w, acc0);  acc1 = fmaf(a1.w, c1.w, acc1);
    acc0 = fmaf(a2.x, c2.x, acc0);  acc1 = fmaf(a3.x, c3.x, acc1);
    acc0 = fmaf(a2.y, c2.y, acc0);  acc1 = fmaf(a3.y, c3.y, acc1);
    acc0 = fmaf(a2.z, c2.z, acc0);  acc1 = fmaf(a3.z, c3.z, acc1);
    acc0 = fmaf(a2.w, c2.w, acc0);  acc1 = fmaf(a3.w, c3.w, acc1);
    float acc = acc0 + acc1;

    // Reduce over the 8-lane group (3 butterfly stages).
    acc += __shfl_xor_sync(0xFFFFFFFFu, acc, 1);
    acc += __shfl_xor_sync(0xFFFFFFFFu, acc, 2);
    acc += __shfl_xor_sync(0xFFFFFFFFu, acc, 4);

    if (sub == 0)
        out[row] = acc + bv1 + bv2;
}

extern "C" void kernel_launch(void* const* d_in, const int* in_sizes, int n_in,
                              void* d_out, int out_size) {
    const int*   i1 = (const int*)d_in[0];
    const int*   i2 = (const int*)d_in[1];
    const float* W1 = (const float*)d_in[2];
    const float* W2 = (const float*)d_in[3];
    const float* b1 = (const float*)d_in[4];
    const float* b2 = (const float*)d_in[5];
    float* out = (float*)d_out;

    // 16384 rows * 8 threads / 256 = 512 blocks (single wave on 148 SMs)
    fused_embed_dot_kernel<<<(BATCH * 8) / 256, 256>>>(i1, i2, W1, W2, b1, b2, out);
}